// round 2
// baseline (speedup 1.0000x reference)
#include <cuda_runtime.h>
#include <cuda_bf16.h>

#define NN    20000
#define EE    320000
#define BB    128
#define DIN   64
#define HH    2
#define CC    64
#define LL    2
#define SLOPE 0.2f
#define EPSBN 1e-5f
#define BN_BLOCKS 100

// ---------------- scratch (device globals; no allocation) ----------------
__device__ float g_xl[NN * 128];            // [N][128] node features (both heads)
__device__ float g_al[NN * HH];
__device__ float g_ar[NN * HH];
__device__ float g_ex[EE * HH];             // exp(leakyrelu(a))
__device__ float g_h[NN * DIN];             // hidden state between layers
__device__ float g_wa[LL * 3 * 128 * HH];   // folded att vectors: [l][{al,ar,ae}][k][h]
__device__ float g_ins_xl[LL * BB * 128];   // ins @ W_l_bottom
__device__ float g_ins_a[LL * 3 * BB * HH]; // ins @ w_{al,ar,ae}_bottom
__device__ int   g_cnt[NN];                 // in-degree histogram
__device__ int   g_start[NN + 1];           // CSR row starts
__device__ int   g_cur[NN];                 // placement cursors
__device__ int   g_csr[EE];                 // edge ids grouped by dst (sorted per bucket)
__device__ float g_bnp[BN_BLOCKS * 64];     // BN partial sums
__device__ float g_bnp2[BN_BLOCKS * 64];    // BN partial sum of squares
__device__ float g_mu[64];
__device__ float g_scale[64];               // gamma * rsqrt(var + eps)

// ---------------- precompute: fold att vectors through W ----------------
__global__ void prep_weights(const float* __restrict__ Wl, const float* __restrict__ We,
                             const float* __restrict__ attl, const float* __restrict__ attr_,
                             const float* __restrict__ atte) {
    int idx = blockIdx.x * blockDim.x + threadIdx.x;
    if (idx >= LL * 3 * 128 * HH) return;
    int l  = idx / (3 * 128 * HH);
    int r  = idx % (3 * 128 * HH);
    int t  = r / (128 * HH);
    int r2 = r % (128 * HH);
    int k  = r2 / HH;
    int h  = r2 % HH;
    const float* W   = (t == 2) ? We : Wl;
    const float* att = (t == 0) ? attl : (t == 1) ? attr_ : atte;
    float acc = 0.f;
#pragma unroll 8
    for (int c = 0; c < CC; c++)
        acc += W[l * 128 * 128 + k * 128 + h * CC + c] * att[l * HH * CC + h * CC + c];
    g_wa[((l * 3 + t) * 128 + k) * HH + h] = acc;
}

// ---------------- precompute: per-graph instruction terms ----------------
__global__ void prep_ins(const float* __restrict__ ins, const float* __restrict__ Wl) {
    int idx = blockIdx.x * blockDim.x + threadIdx.x;
    const int NXL = LL * BB * 128;
    if (idx < NXL) {
        int l = idx / (BB * 128);
        int r = idx % (BB * 128);
        int b = r / 128;
        int m = r % 128;
        float acc = 0.f;
#pragma unroll 8
        for (int k = 0; k < DIN; k++)
            acc += ins[(l * BB + b) * DIN + k] * Wl[l * 128 * 128 + (64 + k) * 128 + m];
        g_ins_xl[(l * BB + b) * 128 + m] = acc;
    } else if (idx < NXL + LL * 3 * BB * HH) {
        int j  = idx - NXL;
        int l  = j / (3 * BB * HH);
        int r  = j % (3 * BB * HH);
        int t  = r / (BB * HH);
        int r2 = r % (BB * HH);
        int b  = r2 / HH;
        int h  = r2 % HH;
        float acc = 0.f;
#pragma unroll 8
        for (int k = 0; k < DIN; k++)
            acc += ins[(l * BB + b) * DIN + k] * g_wa[((l * 3 + t) * 128 + 64 + k) * HH + h];
        g_ins_a[((l * 3 + t) * BB + b) * HH + h] = acc;
    }
}

// ---------------- CSR build: zero, histogram, scan, place, sort ----------------
__global__ void zero_cnt() {
    int n = blockIdx.x * blockDim.x + threadIdx.x;
    if (n < NN) g_cnt[n] = 0;
}

__global__ void hist_kernel(const int* __restrict__ ei) {
    int e = blockIdx.x * blockDim.x + threadIdx.x;
    if (e < EE) atomicAdd(&g_cnt[ei[EE + e]], 1);
}

__global__ __launch_bounds__(1024) void scan_kernel() {
    __shared__ int sh[1024];
    const int NPT = 20;  // 1024 * 20 = 20480 >= NN
    int t = threadIdx.x;
    int base = t * NPT;
    int loc[NPT];
    int sum = 0;
#pragma unroll
    for (int i = 0; i < NPT; i++) {
        int n = base + i;
        int cv = (n < NN) ? g_cnt[n] : 0;
        loc[i] = sum;
        sum += cv;
    }
    sh[t] = sum;
    __syncthreads();
    for (int off = 1; off < 1024; off <<= 1) {
        int v = (t >= off) ? sh[t - off] : 0;
        __syncthreads();
        sh[t] += v;
        __syncthreads();
    }
    int pre = (t > 0) ? sh[t - 1] : 0;
#pragma unroll
    for (int i = 0; i < NPT; i++) {
        int n = base + i;
        if (n < NN) {
            int v = pre + loc[i];
            g_start[n] = v;
            g_cur[n] = v;
        }
    }
    if (t == 1023) g_start[NN] = sh[1023];
}

__global__ void place_kernel(const int* __restrict__ ei) {
    int e = blockIdx.x * blockDim.x + threadIdx.x;
    if (e >= EE) return;
    int d = ei[EE + e];
    int pos = atomicAdd(&g_cur[d], 1);
    g_csr[pos] = e;
}

// canonicalize bucket order (insertion sort by edge id) -> deterministic sums
__global__ void sort_kernel() {
    int n = blockIdx.x * blockDim.x + threadIdx.x;
    if (n >= NN) return;
    int s = g_start[n], e = g_start[n + 1];
    for (int i = s + 1; i < e; i++) {
        int v = g_csr[i];
        int j = i - 1;
        while (j >= s && g_csr[j] > v) {
            g_csr[j + 1] = g_csr[j];
            j--;
        }
        g_csr[j + 1] = v;
    }
}

// ---------------- node kernel: xl, al, ar ----------------
__global__ __launch_bounds__(128) void node_kernel(
    const float* __restrict__ x, const int* __restrict__ batch,
    const float* __restrict__ Wl, int l, int use_x) {
    __shared__ __align__(16) float hs[64][16];   // [k][n]
    __shared__ int bsm[16];
    const float* hin = use_x ? x : g_h;
    int node0 = blockIdx.x * 16;
    int t = threadIdx.x;
#pragma unroll
    for (int i = t; i < 16 * 64; i += 128) {
        int n = i >> 6, k = i & 63;
        hs[k][n] = hin[(node0 + n) * DIN + k];
    }
    if (t < 16) bsm[t] = batch[node0 + t];
    __syncthreads();

    int m = t;  // output column 0..127
    float acc[16];
#pragma unroll
    for (int n = 0; n < 16; n++)
        acc[n] = g_ins_xl[(l * BB + bsm[n]) * 128 + m];

    const float* Wtop = Wl + l * 128 * 128;
#pragma unroll 4
    for (int k = 0; k < 64; k++) {
        float w = Wtop[k * 128 + m];
        float4 a = *(const float4*)&hs[k][0];
        float4 b = *(const float4*)&hs[k][4];
        float4 c = *(const float4*)&hs[k][8];
        float4 d = *(const float4*)&hs[k][12];
        acc[0]  += a.x * w; acc[1]  += a.y * w; acc[2]  += a.z * w; acc[3]  += a.w * w;
        acc[4]  += b.x * w; acc[5]  += b.y * w; acc[6]  += b.z * w; acc[7]  += b.w * w;
        acc[8]  += c.x * w; acc[9]  += c.y * w; acc[10] += c.z * w; acc[11] += c.w * w;
        acc[12] += d.x * w; acc[13] += d.y * w; acc[14] += d.z * w; acc[15] += d.w * w;
    }
#pragma unroll
    for (int n = 0; n < 16; n++)
        g_xl[(node0 + n) * 128 + m] = acc[n];

    if (t < 64) {
        int n  = t >> 2;
        int q  = t & 3;
        int ta = q >> 1;
        int hh = q & 1;
        float a2 = 0.f;
        const float* w = &g_wa[((l * 3 + ta) * 128) * HH + hh];
#pragma unroll 8
        for (int k = 0; k < 64; k++)
            a2 += hs[k][n] * w[k * HH];
        a2 += g_ins_a[((l * 3 + ta) * BB + bsm[n]) * HH + hh];
        float* dst = (ta == 0) ? g_al : g_ar;
        dst[(node0 + n) * HH + hh] = a2;
    }
}

// ---------------- edge pass: ae -> a -> leakyrelu -> exp (no atomics) ----------------
__global__ __launch_bounds__(256) void edgeA_kernel(
    const int* __restrict__ ei, const float* __restrict__ ea,
    const int* __restrict__ batch, int l) {
    int warp = threadIdx.x >> 5, lane = threadIdx.x & 31;
    int e = blockIdx.x * 8 + warp;
    float ea0 = ea[e * 64 + lane];
    float ea1 = ea[e * 64 + 32 + lane];
    const float* w = &g_wa[((l * 3 + 2) * 128) * HH];
    float w00 = w[lane * 2], w01 = w[lane * 2 + 1];
    float w10 = w[(lane + 32) * 2], w11 = w[(lane + 32) * 2 + 1];
    float p0 = ea0 * w00 + ea1 * w10;
    float p1 = ea0 * w01 + ea1 * w11;
#pragma unroll
    for (int off = 16; off; off >>= 1) {
        p0 += __shfl_xor_sync(0xffffffffu, p0, off);
        p1 += __shfl_xor_sync(0xffffffffu, p1, off);
    }
    if (lane == 0) {
        int s = ei[e], d = ei[EE + e];
        int b = batch[s];
        float a0 = p0 + g_ins_a[((l * 3 + 2) * BB + b) * HH + 0] + g_al[s * 2] + g_ar[d * 2];
        float a1 = p1 + g_ins_a[((l * 3 + 2) * BB + b) * HH + 1] + g_al[s * 2 + 1] + g_ar[d * 2 + 1];
        a0 = a0 > 0.f ? a0 : SLOPE * a0;
        a1 = a1 > 0.f ? a1 : SLOPE * a1;
        g_ex[e * 2]     = __expf(a0);
        g_ex[e * 2 + 1] = __expf(a1);
    }
}

// ---------------- gather: warp per node, deterministic order ----------------
__global__ __launch_bounds__(256) void gather_kernel(
    const float* __restrict__ x, const float* __restrict__ bias,
    float* __restrict__ dout, const int* __restrict__ ei,
    int l, int use_x, int do_bn) {
    int warp = threadIdx.x >> 5, lane = threadIdx.x & 31;
    int n = blockIdx.x * 8 + warp;
    const float* hin = use_x ? x : g_h;
    float* hout = do_bn ? g_h : dout;
    int s0 = g_start[n], s1 = g_start[n + 1];

    // softmax denominators (fixed-order strided + shuffle tree -> deterministic)
    float ss0 = 0.f, ss1 = 0.f;
    for (int i = s0 + lane; i < s1; i += 32) {
        int e = g_csr[i];
        ss0 += g_ex[e * 2];
        ss1 += g_ex[e * 2 + 1];
    }
#pragma unroll
    for (int off = 16; off; off >>= 1) {
        ss0 += __shfl_xor_sync(0xffffffffu, ss0, off);
        ss1 += __shfl_xor_sync(0xffffffffu, ss1, off);
    }
    float inv0 = 0.5f / (ss0 + 1e-16f);
    float inv1 = 0.5f / (ss1 + 1e-16f);

    // alpha-weighted, head-meaned aggregation (sequential in-bucket -> deterministic)
    float a0 = 0.f, a1 = 0.f;
    for (int i = s0; i < s1; i++) {
        int e = g_csr[i];
        int src = ei[e];
        float w0 = g_ex[e * 2] * inv0;
        float w1 = g_ex[e * 2 + 1] * inv1;
        const float* xr = g_xl + src * 128;
        a0 += w0 * xr[lane]      + w1 * xr[64 + lane];
        a1 += w0 * xr[32 + lane] + w1 * xr[96 + lane];
    }
    int c0 = lane, c1 = lane + 32;
    float r0 = a0 + bias[l * CC + c0] + hin[n * DIN + c0];
    float r1 = a1 + bias[l * CC + c1] + hin[n * DIN + c1];
    hout[n * DIN + c0] = r0;
    hout[n * DIN + c1] = r1;
}

// ---------------- BN: deterministic two-stage stats + apply ----------------
__global__ __launch_bounds__(256) void bn_stats() {
    __shared__ float s1[256], s2m[256];
    int t = threadIdx.x;
    int c = t & 63, slot = t >> 6;
    float su = 0.f, sq = 0.f;
    for (int n = blockIdx.x * 4 + slot; n < NN; n += BN_BLOCKS * 4) {
        float v = g_h[n * DIN + c];
        su += v;
        sq += v * v;
    }
    s1[t] = su; s2m[t] = sq;
    __syncthreads();
    if (t < 64) {
        float a = s1[t] + s1[t + 64] + s1[t + 128] + s1[t + 192];
        float b = s2m[t] + s2m[t + 64] + s2m[t + 128] + s2m[t + 192];
        g_bnp[blockIdx.x * 64 + t]  = a;
        g_bnp2[blockIdx.x * 64 + t] = b;
    }
}

__global__ void bn_finalize(const float* __restrict__ gamma) {
    int c = threadIdx.x;
    if (c >= 64) return;
    float su = 0.f, sq = 0.f;
    for (int b = 0; b < BN_BLOCKS; b++) {
        su += g_bnp[b * 64 + c];
        sq += g_bnp2[b * 64 + c];
    }
    float mu = su / (float)NN;
    float var = sq / (float)NN - mu * mu;
    g_mu[c] = mu;
    g_scale[c] = gamma[c] * rsqrtf(var + EPSBN);
}

__global__ __launch_bounds__(256) void bn_apply(const float* __restrict__ beta) {
    int idx = blockIdx.x * blockDim.x + threadIdx.x;
    if (idx >= NN * DIN) return;
    int c = idx & 63;
    float v = (g_h[idx] - g_mu[c]) * g_scale[c] + beta[c];
    g_h[idx] = v > 0.f ? v : 0.f;
}

extern "C" void kernel_launch(void* const* d_in, const int* in_sizes, int n_in,
                              void* d_out, int out_size) {
    const float* x     = (const float*)d_in[0];
    const int*   ei    = (const int*)  d_in[1];
    const float* ea    = (const float*)d_in[2];
    const float* ins   = (const float*)d_in[3];
    const int*   batch = (const int*)  d_in[4];
    const float* Wl    = (const float*)d_in[5];
    const float* We    = (const float*)d_in[6];
    const float* attl  = (const float*)d_in[7];
    const float* attr_ = (const float*)d_in[8];
    const float* atte  = (const float*)d_in[9];
    const float* bias  = (const float*)d_in[10];
    const float* gamma = (const float*)d_in[11];
    const float* beta  = (const float*)d_in[12];
    float* out = (float*)d_out;

    prep_weights<<<(LL * 3 * 128 * HH + 255) / 256, 256>>>(Wl, We, attl, attr_, atte);
    prep_ins<<<(LL * BB * 128 + LL * 3 * BB * HH + 255) / 256, 256>>>(ins, Wl);

    // CSR build (deterministic canonical order)
    zero_cnt<<<(NN + 255) / 256, 256>>>();
    hist_kernel<<<(EE + 255) / 256, 256>>>(ei);
    scan_kernel<<<1, 1024>>>();
    place_kernel<<<(EE + 255) / 256, 256>>>(ei);
    sort_kernel<<<(NN + 255) / 256, 256>>>();

    for (int l = 0; l < LL; l++) {
        int use_x = (l == 0);
        int do_bn = (l != LL - 1);
        node_kernel<<<NN / 16, 128>>>(x, batch, Wl, l, use_x);
        edgeA_kernel<<<EE / 8, 256>>>(ei, ea, batch, l);
        gather_kernel<<<NN / 8, 256>>>(x, bias, out, ei, l, use_x, do_bn);
        if (do_bn) {
            bn_stats<<<BN_BLOCKS, 256>>>();
            bn_finalize<<<1, 64>>>(gamma);
            bn_apply<<<(NN * DIN + 255) / 256, 256>>>(beta);
        }
    }
}

// round 4
// speedup vs baseline: 1.4605x; 1.4605x over previous
#include <cuda_runtime.h>
#include <cuda_bf16.h>

#define NN    20000
#define EE    320000
#define BB    128
#define DIN   64
#define HH    2
#define CC    64
#define LL    2
#define SLOPE 0.2f
#define EPSBN 1e-5f
#define BN_BLOCKS 100
#define SCAN_B 79   // ceil(NN/256)

// ---------------- scratch (device globals; no allocation) ----------------
__device__ float g_xl[NN * 128];            // [N][128] node features (both heads)
__device__ float g_al[NN * HH];
__device__ float g_ar[NN * HH];
__device__ float g_pe[LL * EE * HH];        // ae dot + ins term, both layers
__device__ float g_ex[EE * HH];             // exp(leakyrelu(a)), current layer
__device__ float g_h[NN * DIN];             // hidden state between layers (pre-BN for l=0)
__device__ float g_wa[LL * 3 * 128 * HH];   // folded att vectors: [l][{al,ar,ae}][k][h]
__device__ float g_ins_xl[LL * BB * 128];   // ins @ W_l_bottom
__device__ float g_ins_a[LL * 3 * BB * HH]; // ins @ w_{al,ar,ae}_bottom
__device__ int   g_cnt[NN];                 // in-degree histogram
__device__ int   g_start[NN + 1];           // CSR row starts
__device__ int   g_cur[NN];                 // placement cursors
__device__ int   g_csr[EE];                 // edge ids grouped by dst (canonical order)
__device__ int   g_bsum[SCAN_B];            // scan block partials
__device__ int   g_boff[SCAN_B];            // scan block offsets
__device__ float g_bnp[BN_BLOCKS * 64];
__device__ float g_bnp2[BN_BLOCKS * 64];
__device__ float g_mu[64];
__device__ float g_scale[64];               // gamma * rsqrt(var + eps)

// ---------------- prep 1: fold att vectors through W; zero histogram ----------------
__global__ void prep_weights(const float* __restrict__ Wl, const float* __restrict__ We,
                             const float* __restrict__ attl, const float* __restrict__ attr_,
                             const float* __restrict__ atte) {
    int idx = blockIdx.x * blockDim.x + threadIdx.x;
    if (idx < NN) g_cnt[idx] = 0;
    if (idx >= LL * 3 * 128 * HH) return;
    int l  = idx / (3 * 128 * HH);
    int r  = idx % (3 * 128 * HH);
    int t  = r / (128 * HH);
    int r2 = r % (128 * HH);
    int k  = r2 / HH;
    int h  = r2 % HH;
    const float* W   = (t == 2) ? We : Wl;
    const float* att = (t == 0) ? attl : (t == 1) ? attr_ : atte;
    float acc = 0.f;
#pragma unroll 8
    for (int c = 0; c < CC; c++)
        acc += W[l * 128 * 128 + k * 128 + h * CC + c] * att[l * HH * CC + h * CC + c];
    g_wa[((l * 3 + t) * 128 + k) * HH + h] = acc;
}

// ---------------- prep 2: per-graph instruction terms + dst histogram ----------------
__global__ void prep_ins(const float* __restrict__ ins, const float* __restrict__ Wl,
                         const int* __restrict__ ei) {
    int idx = blockIdx.x * blockDim.x + threadIdx.x;
    const int NXL = LL * BB * 128;
    if (idx < NXL) {
        int l = idx / (BB * 128);
        int r = idx % (BB * 128);
        int b = r / 128;
        int m = r % 128;
        float acc = 0.f;
#pragma unroll 8
        for (int k = 0; k < DIN; k++)
            acc += ins[(l * BB + b) * DIN + k] * Wl[l * 128 * 128 + (64 + k) * 128 + m];
        g_ins_xl[(l * BB + b) * 128 + m] = acc;
    } else if (idx < NXL + LL * 3 * BB * HH) {
        int j  = idx - NXL;
        int l  = j / (3 * BB * HH);
        int r  = j % (3 * BB * HH);
        int t  = r / (BB * HH);
        int r2 = r % (BB * HH);
        int b  = r2 / HH;
        int h  = r2 % HH;
        float acc = 0.f;
#pragma unroll 8
        for (int k = 0; k < DIN; k++)
            acc += ins[(l * BB + b) * DIN + k] * g_wa[((l * 3 + t) * 128 + 64 + k) * HH + h];
        g_ins_a[((l * 3 + t) * BB + b) * HH + h] = acc;
    }
    if (idx < EE) atomicAdd(&g_cnt[ei[EE + idx]], 1);
}

// ---------------- scan (3-phase, multi-block) ----------------
__global__ __launch_bounds__(256) void scanA() {
    __shared__ int sh[256];
    int t = threadIdx.x;
    int n = blockIdx.x * 256 + t;
    sh[t] = (n < NN) ? g_cnt[n] : 0;
    __syncthreads();
#pragma unroll
    for (int off = 128; off; off >>= 1) {
        if (t < off) sh[t] += sh[t + off];
        __syncthreads();
    }
    if (t == 0) g_bsum[blockIdx.x] = sh[0];
}

__global__ __launch_bounds__(128) void scanB() {
    __shared__ int sh[128];
    int t = threadIdx.x;
    sh[t] = (t < SCAN_B) ? g_bsum[t] : 0;
    __syncthreads();
    for (int off = 1; off < 128; off <<= 1) {
        int v = (t >= off) ? sh[t - off] : 0;
        __syncthreads();
        sh[t] += v;
        __syncthreads();
    }
    if (t < SCAN_B) g_boff[t] = sh[t] - g_bsum[t];   // exclusive
}

__global__ __launch_bounds__(256) void scanC() {
    __shared__ int sh[256];
    int t = threadIdx.x;
    int n = blockIdx.x * 256 + t;
    int v = (n < NN) ? g_cnt[n] : 0;
    sh[t] = v;
    __syncthreads();
    for (int off = 1; off < 256; off <<= 1) {
        int u = (t >= off) ? sh[t - off] : 0;
        __syncthreads();
        sh[t] += u;
        __syncthreads();
    }
    if (n < NN) {
        int start = g_boff[blockIdx.x] + sh[t] - v;   // exclusive within block
        g_start[n] = start;
        g_cur[n] = start;
        if (n == NN - 1) g_start[NN] = start + v;
    }
}

__global__ void place_kernel(const int* __restrict__ ei) {
    int e = blockIdx.x * blockDim.x + threadIdx.x;
    if (e >= EE) return;
    int d = ei[EE + e];
    int pos = atomicAdd(&g_cur[d], 1);
    g_csr[pos] = e;
}

// ---------------- canonicalize bucket order: warp rank sort ----------------
__global__ __launch_bounds__(256) void sort_kernel() {
    int warp = threadIdx.x >> 5, lane = threadIdx.x & 31;
    int n = blockIdx.x * 8 + warp;
    if (n >= NN) return;
    int s0 = g_start[n], s1 = g_start[n + 1];
    int d = s1 - s0;
    if (d <= 1) return;
    if (d <= 32) {
        int v = (lane < d) ? g_csr[s0 + lane] : 0x7fffffff;
        int rank = 0;
#pragma unroll
        for (int j = 0; j < 32; j++) {
            int u = __shfl_sync(0xffffffffu, v, j);
            rank += (u < v);
        }
        __syncwarp();
        if (lane < d) g_csr[s0 + rank] = v;
    } else if (lane == 0) {
        for (int i = s0 + 1; i < s1; i++) {
            int v = g_csr[i];
            int j = i - 1;
            while (j >= s0 && g_csr[j] > v) { g_csr[j + 1] = g_csr[j]; j--; }
            g_csr[j + 1] = v;
        }
    }
}

// ---------------- edge precompute (ONCE): ae dot + ins terms, both layers ----------------
__global__ __launch_bounds__(256) void edge_pre(
    const int* __restrict__ ei, const float* __restrict__ ea,
    const int* __restrict__ batch) {
    int warp = threadIdx.x >> 5, lane = threadIdx.x & 31;
    int e = blockIdx.x * 8 + warp;
    float ea0 = ea[e * 64 + lane];
    float ea1 = ea[e * 64 + 32 + lane];
    float p[LL][HH];
#pragma unroll
    for (int l = 0; l < LL; l++) {
        const float* w = &g_wa[((l * 3 + 2) * 128) * HH];
#pragma unroll
        for (int h = 0; h < HH; h++)
            p[l][h] = ea0 * w[lane * 2 + h] + ea1 * w[(lane + 32) * 2 + h];
    }
#pragma unroll
    for (int off = 16; off; off >>= 1)
#pragma unroll
        for (int l = 0; l < LL; l++)
#pragma unroll
            for (int h = 0; h < HH; h++)
                p[l][h] += __shfl_xor_sync(0xffffffffu, p[l][h], off);
    if (lane == 0) {
        int s = ei[e];
        int b = batch[s];
#pragma unroll
        for (int l = 0; l < LL; l++) {
            float2 v;
            v.x = p[l][0] + g_ins_a[((l * 3 + 2) * BB + b) * HH + 0];
            v.y = p[l][1] + g_ins_a[((l * 3 + 2) * BB + b) * HH + 1];
            *(float2*)&g_pe[(l * EE + e) * 2] = v;
        }
    }
}

// ---------------- node kernel: xl, al, ar (optional fused BN+relu on input) ----------------
__global__ __launch_bounds__(128) void node_kernel(
    const float* __restrict__ x, const int* __restrict__ batch,
    const float* __restrict__ Wl, const float* __restrict__ beta,
    int l, int use_x, int bn_in) {
    __shared__ __align__(16) float hs[64][16];   // [k][n]
    __shared__ int bsm[16];
    const float* hin = use_x ? x : g_h;
    int node0 = blockIdx.x * 16;
    int t = threadIdx.x;
#pragma unroll
    for (int i = t; i < 16 * 64; i += 128) {
        int n = i >> 6, k = i & 63;
        float v = hin[(node0 + n) * DIN + k];
        if (bn_in) {
            v = (v - g_mu[k]) * g_scale[k] + beta[k];
            v = v > 0.f ? v : 0.f;
        }
        hs[k][n] = v;
    }
    if (t < 16) bsm[t] = batch[node0 + t];
    __syncthreads();

    int m = t;  // output column 0..127
    float acc[16];
#pragma unroll
    for (int n = 0; n < 16; n++)
        acc[n] = g_ins_xl[(l * BB + bsm[n]) * 128 + m];

    const float* Wtop = Wl + l * 128 * 128;
#pragma unroll 4
    for (int k = 0; k < 64; k++) {
        float w = Wtop[k * 128 + m];
        float4 a = *(const float4*)&hs[k][0];
        float4 b = *(const float4*)&hs[k][4];
        float4 c = *(const float4*)&hs[k][8];
        float4 d = *(const float4*)&hs[k][12];
        acc[0]  += a.x * w; acc[1]  += a.y * w; acc[2]  += a.z * w; acc[3]  += a.w * w;
        acc[4]  += b.x * w; acc[5]  += b.y * w; acc[6]  += b.z * w; acc[7]  += b.w * w;
        acc[8]  += c.x * w; acc[9]  += c.y * w; acc[10] += c.z * w; acc[11] += c.w * w;
        acc[12] += d.x * w; acc[13] += d.y * w; acc[14] += d.z * w; acc[15] += d.w * w;
    }
#pragma unroll
    for (int n = 0; n < 16; n++)
        g_xl[(node0 + n) * 128 + m] = acc[n];

    if (t < 64) {
        int n  = t >> 2;
        int q  = t & 3;
        int ta = q >> 1;
        int hh = q & 1;
        float a2 = 0.f;
        const float* w = &g_wa[((l * 3 + ta) * 128) * HH + hh];
#pragma unroll 8
        for (int k = 0; k < 64; k++)
            a2 += hs[k][n] * w[k * HH];
        a2 += g_ins_a[((l * 3 + ta) * BB + bsm[n]) * HH + hh];
        float* dst = (ta == 0) ? g_al : g_ar;
        dst[(node0 + n) * HH + hh] = a2;
    }
}

// ---------------- per-layer edge combine: a -> leakyrelu -> exp ----------------
__global__ __launch_bounds__(256) void edge_combine(const int* __restrict__ ei, int l) {
    int e = blockIdx.x * 256 + threadIdx.x;
    int s = ei[e], d = ei[EE + e];
    float2 pe = *(const float2*)&g_pe[(l * EE + e) * 2];
    float2 al = *(const float2*)&g_al[s * 2];
    float2 ar = *(const float2*)&g_ar[d * 2];
    float a0 = pe.x + al.x + ar.x;
    float a1 = pe.y + al.y + ar.y;
    a0 = a0 > 0.f ? a0 : SLOPE * a0;
    a1 = a1 > 0.f ? a1 : SLOPE * a1;
    float2 ex;
    ex.x = __expf(a0);
    ex.y = __expf(a1);
    *(float2*)&g_ex[e * 2] = ex;
}

// ---------------- gather: warp per node, shuffle-broadcast metadata ----------------
__global__ __launch_bounds__(256) void gather_kernel(
    const float* __restrict__ x, const float* __restrict__ bias,
    const float* __restrict__ beta, float* __restrict__ dout,
    const int* __restrict__ ei, int l, int use_x, int bn_in, int do_bn_out) {
    int warp = threadIdx.x >> 5, lane = threadIdx.x & 31;
    int n = blockIdx.x * 8 + warp;
    const float* hin = use_x ? x : g_h;
    float* hout = do_bn_out ? g_h : dout;
    int s0 = g_start[n], s1 = g_start[n + 1];

    // batched metadata load: lane i owns edge s0+i
    int i = s0 + lane;
    int src = 0;
    float ex0 = 0.f, ex1 = 0.f;
    if (i < s1) {
        int e = g_csr[i];
        src = ei[e];
        float2 t = *(const float2*)&g_ex[e * 2];
        ex0 = t.x; ex1 = t.y;
    }
    float ss0 = ex0, ss1 = ex1;
    for (int base = s0 + 32; base < s1; base += 32) {   // rare (deg > 32)
        int j = base + lane;
        if (j < s1) {
            int e = g_csr[j];
            float2 t = *(const float2*)&g_ex[e * 2];
            ss0 += t.x; ss1 += t.y;
        }
    }
#pragma unroll
    for (int off = 16; off; off >>= 1) {
        ss0 += __shfl_xor_sync(0xffffffffu, ss0, off);
        ss1 += __shfl_xor_sync(0xffffffffu, ss1, off);
    }
    float inv0 = 0.5f / (ss0 + 1e-16f);
    float inv1 = 0.5f / (ss1 + 1e-16f);

    float acc0 = 0.f, acc1 = 0.f;
    int dc = s1 - s0; if (dc > 32) dc = 32;
#pragma unroll 4
    for (int k = 0; k < dc; k++) {
        float w0 = __shfl_sync(0xffffffffu, ex0, k) * inv0;
        float w1 = __shfl_sync(0xffffffffu, ex1, k) * inv1;
        int sj   = __shfl_sync(0xffffffffu, src, k);
        const float* xr = g_xl + sj * 128;
        acc0 += w0 * xr[lane]      + w1 * xr[64 + lane];
        acc1 += w0 * xr[32 + lane] + w1 * xr[96 + lane];
    }
    for (int j = s0 + 32; j < s1; j++) {               // rare tail
        int e = g_csr[j];
        int sj = ei[e];
        float w0 = g_ex[e * 2] * inv0;
        float w1 = g_ex[e * 2 + 1] * inv1;
        const float* xr = g_xl + sj * 128;
        acc0 += w0 * xr[lane]      + w1 * xr[64 + lane];
        acc1 += w0 * xr[32 + lane] + w1 * xr[96 + lane];
    }

    int c0 = lane, c1 = lane + 32;
    float h0 = hin[n * DIN + c0];
    float h1 = hin[n * DIN + c1];
    if (bn_in) {
        h0 = (h0 - g_mu[c0]) * g_scale[c0] + beta[c0]; h0 = h0 > 0.f ? h0 : 0.f;
        h1 = (h1 - g_mu[c1]) * g_scale[c1] + beta[c1]; h1 = h1 > 0.f ? h1 : 0.f;
    }
    hout[n * DIN + c0] = acc0 + bias[l * CC + c0] + h0;
    hout[n * DIN + c1] = acc1 + bias[l * CC + c1] + h1;
}

// ---------------- BN stats (deterministic two-stage) ----------------
__global__ __launch_bounds__(256) void bn_stats() {
    __shared__ float s1[256], s2m[256];
    int t = threadIdx.x;
    int c = t & 63, slot = t >> 6;
    float su = 0.f, sq = 0.f;
    for (int n = blockIdx.x * 4 + slot; n < NN; n += BN_BLOCKS * 4) {
        float v = g_h[n * DIN + c];
        su += v;
        sq += v * v;
    }
    s1[t] = su; s2m[t] = sq;
    __syncthreads();
    if (t < 64) {
        g_bnp[blockIdx.x * 64 + t]  = s1[t] + s1[t + 64] + s1[t + 128] + s1[t + 192];
        g_bnp2[blockIdx.x * 64 + t] = s2m[t] + s2m[t + 64] + s2m[t + 128] + s2m[t + 192];
    }
}

__global__ void bn_finalize(const float* __restrict__ gamma) {
    int c = threadIdx.x;
    if (c >= 64) return;
    float su = 0.f, sq = 0.f;
    for (int b = 0; b < BN_BLOCKS; b++) {
        su += g_bnp[b * 64 + c];
        sq += g_bnp2[b * 64 + c];
    }
    float mu = su / (float)NN;
    float var = sq / (float)NN - mu * mu;
    g_mu[c] = mu;
    g_scale[c] = gamma[c] * rsqrtf(var + EPSBN);
}

extern "C" void kernel_launch(void* const* d_in, const int* in_sizes, int n_in,
                              void* d_out, int out_size) {
    const float* x     = (const float*)d_in[0];
    const int*   ei    = (const int*)  d_in[1];
    const float* ea    = (const float*)d_in[2];
    const float* ins   = (const float*)d_in[3];
    const int*   batch = (const int*)  d_in[4];
    const float* Wl    = (const float*)d_in[5];
    const float* We    = (const float*)d_in[6];
    const float* attl  = (const float*)d_in[7];
    const float* attr_ = (const float*)d_in[8];
    const float* atte  = (const float*)d_in[9];
    const float* bias  = (const float*)d_in[10];
    const float* gamma = (const float*)d_in[11];
    const float* beta  = (const float*)d_in[12];
    float* out = (float*)d_out;

    prep_weights<<<SCAN_B, 256>>>(Wl, We, attl, attr_, atte);          // + zero cnt
    prep_ins<<<EE / 256, 256>>>(ins, Wl, ei);                          // + histogram
    scanA<<<SCAN_B, 256>>>();
    scanB<<<1, 128>>>();
    scanC<<<SCAN_B, 256>>>();
    place_kernel<<<EE / 256, 256>>>(ei);
    sort_kernel<<<NN / 8, 256>>>();
    edge_pre<<<EE / 8, 256>>>(ei, ea, batch);

    for (int l = 0; l < LL; l++) {
        int use_x = (l == 0);
        int bn_in = (l > 0);
        int do_bn_out = (l != LL - 1);
        node_kernel<<<NN / 16, 128>>>(x, batch, Wl, beta, l, use_x, bn_in);
        edge_combine<<<EE / 256, 256>>>(ei, l);
        gather_kernel<<<NN / 8, 256>>>(x, bias, beta, out, ei, l, use_x, bn_in, do_bn_out);
        if (do_bn_out) {
            bn_stats<<<BN_BLOCKS, 256>>>();
            bn_finalize<<<1, 64>>>(gamma);
        }
    }
}

// round 6
// speedup vs baseline: 1.5053x; 1.0307x over previous
#include <cuda_runtime.h>
#include <cuda_bf16.h>

#define NN    20000
#define EE    320000
#define BB    128
#define DIN   64
#define HH    2
#define CC    64
#define LL    2
#define SLOPE 0.2f
#define EPSBN 1e-5f
#define BN_BLOCKS 100
#define SCAN_B 79   // ceil(NN/256)

// ---------------- scratch (device globals; no allocation) ----------------
__device__ float g_xl[NN * 128];            // [N][128] node features (both heads)
__device__ float g_al[NN * HH];
__device__ float g_ar[NN * HH];
__device__ float g_pe[LL * EE * HH];        // ae dot + ins term, both layers
__device__ float g_h[NN * DIN];             // hidden state between layers (pre-BN for l=0)
__device__ float g_wa[LL * 3 * 128 * HH];   // folded att vectors: [l][{al,ar,ae}][k][h]
__device__ float g_ins_xl[LL * BB * 128];   // ins @ W_l_bottom
__device__ float g_ins_a[LL * 3 * BB * HH]; // ins @ w_{al,ar,ae}_bottom
__device__ int   g_cnt[NN];                 // in-degree histogram
__device__ int   g_start[NN + 1];           // CSR row starts
__device__ int   g_cur[NN];                 // placement cursors
__device__ int   g_csr[EE];                 // edge ids grouped by dst (canonical order)
__device__ int   g_bsum[SCAN_B];            // scan block partials
__device__ float g_bnp[BN_BLOCKS * 64];
__device__ float g_bnp2[BN_BLOCKS * 64];
__device__ float g_mu[64];
__device__ float g_scale[64];               // gamma * rsqrt(var + eps)

// ---------------- prep 1: fold att vectors through W; zero histogram ----------------
__global__ void prep_weights(const float* __restrict__ Wl, const float* __restrict__ We,
                             const float* __restrict__ attl, const float* __restrict__ attr_,
                             const float* __restrict__ atte) {
    int idx = blockIdx.x * blockDim.x + threadIdx.x;
    if (idx < NN) g_cnt[idx] = 0;
    if (idx >= LL * 3 * 128 * HH) return;
    int l  = idx / (3 * 128 * HH);
    int r  = idx % (3 * 128 * HH);
    int t  = r / (128 * HH);
    int r2 = r % (128 * HH);
    int k  = r2 / HH;
    int h  = r2 % HH;
    const float* W   = (t == 2) ? We : Wl;
    const float* att = (t == 0) ? attl : (t == 1) ? attr_ : atte;
    float acc = 0.f;
#pragma unroll 8
    for (int c = 0; c < CC; c++)
        acc += W[l * 128 * 128 + k * 128 + h * CC + c] * att[l * HH * CC + h * CC + c];
    g_wa[((l * 3 + t) * 128 + k) * HH + h] = acc;
}

// ---------------- prep 2: per-graph instruction terms + dst histogram ----------------
__global__ void prep_ins(const float* __restrict__ ins, const float* __restrict__ Wl,
                         const int* __restrict__ ei) {
    int idx = blockIdx.x * blockDim.x + threadIdx.x;
    const int NXL = LL * BB * 128;
    if (idx < NXL) {
        int l = idx / (BB * 128);
        int r = idx % (BB * 128);
        int b = r / 128;
        int m = r % 128;
        float acc = 0.f;
#pragma unroll 8
        for (int k = 0; k < DIN; k++)
            acc += ins[(l * BB + b) * DIN + k] * Wl[l * 128 * 128 + (64 + k) * 128 + m];
        g_ins_xl[(l * BB + b) * 128 + m] = acc;
    } else if (idx < NXL + LL * 3 * BB * HH) {
        int j  = idx - NXL;
        int l  = j / (3 * BB * HH);
        int r  = j % (3 * BB * HH);
        int t  = r / (BB * HH);
        int r2 = r % (BB * HH);
        int b  = r2 / HH;
        int h  = r2 % HH;
        float acc = 0.f;
#pragma unroll 8
        for (int k = 0; k < DIN; k++)
            acc += ins[(l * BB + b) * DIN + k] * g_wa[((l * 3 + t) * 128 + 64 + k) * HH + h];
        g_ins_a[((l * 3 + t) * BB + b) * HH + h] = acc;
    }
    if (idx < EE) atomicAdd(&g_cnt[ei[EE + idx]], 1);
}

// ---------------- scan phase A: per-block sums ----------------
__global__ __launch_bounds__(256) void scanA() {
    __shared__ int sh[256];
    int t = threadIdx.x;
    int n = blockIdx.x * 256 + t;
    sh[t] = (n < NN) ? g_cnt[n] : 0;
    __syncthreads();
#pragma unroll
    for (int off = 128; off; off >>= 1) {
        if (t < off) sh[t] += sh[t + off];
        __syncthreads();
    }
    if (t == 0) g_bsum[blockIdx.x] = sh[0];
}

// ---------------- scan phase C: block offset (inline) + intra-block scan ----------------
__global__ __launch_bounds__(256) void scanC() {
    __shared__ int sh[256];
    __shared__ int soff;
    int t = threadIdx.x;
    int n = blockIdx.x * 256 + t;
    int v = (n < NN) ? g_cnt[n] : 0;
    if (t < 32) {   // warp 0: offset = sum of preceding block sums
        int off = 0;
        for (int j = t; j < (int)blockIdx.x; j += 32) off += g_bsum[j];
#pragma unroll
        for (int o = 16; o; o >>= 1) off += __shfl_xor_sync(0xffffffffu, off, o);
        if (t == 0) soff = off;
    }
    sh[t] = v;
    __syncthreads();
    for (int off = 1; off < 256; off <<= 1) {
        int u = (t >= off) ? sh[t - off] : 0;
        __syncthreads();
        sh[t] += u;
        __syncthreads();
    }
    if (n < NN) {
        int start = soff + sh[t] - v;   // exclusive within block
        g_start[n] = start;
        g_cur[n] = start;
        if (n == NN - 1) g_start[NN] = start + v;
    }
}

__global__ void place_kernel(const int* __restrict__ ei) {
    int e = blockIdx.x * blockDim.x + threadIdx.x;
    if (e >= EE) return;
    int d = ei[EE + e];
    int pos = atomicAdd(&g_cur[d], 1);
    g_csr[pos] = e;
}

// ---------------- canonicalize bucket order: warp rank sort ----------------
__global__ __launch_bounds__(256) void sort_kernel() {
    int warp = threadIdx.x >> 5, lane = threadIdx.x & 31;
    int n = blockIdx.x * 8 + warp;
    if (n >= NN) return;
    int s0 = g_start[n], s1 = g_start[n + 1];
    int d = s1 - s0;
    if (d <= 1) return;
    if (d <= 32) {
        int v = (lane < d) ? g_csr[s0 + lane] : 0x7fffffff;
        int rank = 0;
#pragma unroll
        for (int j = 0; j < 32; j++) {
            int u = __shfl_sync(0xffffffffu, v, j);
            rank += (u < v);
        }
        __syncwarp();
        if (lane < d) g_csr[s0 + rank] = v;
    } else if (lane == 0) {
        for (int i = s0 + 1; i < s1; i++) {
            int v = g_csr[i];
            int j = i - 1;
            while (j >= s0 && g_csr[j] > v) { g_csr[j + 1] = g_csr[j]; j--; }
            g_csr[j + 1] = v;
        }
    }
}

// ---------------- edge precompute (ONCE): ae dot + ins terms, both layers ----------------
__global__ __launch_bounds__(256) void edge_pre(
    const int* __restrict__ ei, const float* __restrict__ ea,
    const int* __restrict__ batch) {
    int warp = threadIdx.x >> 5, lane = threadIdx.x & 31;
    int e = blockIdx.x * 8 + warp;
    float ea0 = ea[e * 64 + lane];
    float ea1 = ea[e * 64 + 32 + lane];
    float p[LL][HH];
#pragma unroll
    for (int l = 0; l < LL; l++) {
        const float* w = &g_wa[((l * 3 + 2) * 128) * HH];
#pragma unroll
        for (int h = 0; h < HH; h++)
            p[l][h] = ea0 * w[lane * 2 + h] + ea1 * w[(lane + 32) * 2 + h];
    }
#pragma unroll
    for (int off = 16; off; off >>= 1)
#pragma unroll
        for (int l = 0; l < LL; l++)
#pragma unroll
            for (int h = 0; h < HH; h++)
                p[l][h] += __shfl_xor_sync(0xffffffffu, p[l][h], off);
    if (lane == 0) {
        int s = ei[e];
        int b = batch[s];
#pragma unroll
        for (int l = 0; l < LL; l++) {
            float2 v;
            v.x = p[l][0] + g_ins_a[((l * 3 + 2) * BB + b) * HH + 0];
            v.y = p[l][1] + g_ins_a[((l * 3 + 2) * BB + b) * HH + 1];
            *(float2*)&g_pe[(l * EE + e) * 2] = v;
        }
    }
}

// ---------------- node kernel: xl, al, ar (optional fused BN+relu on input) ----------------
__global__ __launch_bounds__(128) void node_kernel(
    const float* __restrict__ x, const int* __restrict__ batch,
    const float* __restrict__ Wl, const float* __restrict__ beta,
    int l, int use_x, int bn_in) {
    __shared__ __align__(16) float hs[64][16];   // [k][n]
    __shared__ int bsm[16];
    const float* hin = use_x ? x : g_h;
    int node0 = blockIdx.x * 16;
    int t = threadIdx.x;
#pragma unroll
    for (int i = t; i < 16 * 64; i += 128) {
        int n = i >> 6, k = i & 63;
        float v = hin[(node0 + n) * DIN + k];
        if (bn_in) {
            v = (v - g_mu[k]) * g_scale[k] + beta[k];
            v = v > 0.f ? v : 0.f;
        }
        hs[k][n] = v;
    }
    if (t < 16) bsm[t] = batch[node0 + t];
    __syncthreads();

    int m = t;  // output column 0..127
    float acc[16];
#pragma unroll
    for (int n = 0; n < 16; n++)
        acc[n] = g_ins_xl[(l * BB + bsm[n]) * 128 + m];

    const float* Wtop = Wl + l * 128 * 128;
#pragma unroll 4
    for (int k = 0; k < 64; k++) {
        float w = Wtop[k * 128 + m];
        float4 a = *(const float4*)&hs[k][0];
        float4 b = *(const float4*)&hs[k][4];
        float4 c = *(const float4*)&hs[k][8];
        float4 d = *(const float4*)&hs[k][12];
        acc[0]  += a.x * w; acc[1]  += a.y * w; acc[2]  += a.z * w; acc[3]  += a.w * w;
        acc[4]  += b.x * w; acc[5]  += b.y * w; acc[6]  += b.z * w; acc[7]  += b.w * w;
        acc[8]  += c.x * w; acc[9]  += c.y * w; acc[10] += c.z * w; acc[11] += c.w * w;
        acc[12] += d.x * w; acc[13] += d.y * w; acc[14] += d.z * w; acc[15] += d.w * w;
    }
#pragma unroll
    for (int n = 0; n < 16; n++)
        g_xl[(node0 + n) * 128 + m] = acc[n];

    if (t < 64) {
        int n  = t >> 2;
        int q  = t & 3;
        int ta = q >> 1;
        int hh = q & 1;
        float a2 = 0.f;
        const float* w = &g_wa[((l * 3 + ta) * 128) * HH + hh];
#pragma unroll 8
        for (int k = 0; k < 64; k++)
            a2 += hs[k][n] * w[k * HH];
        a2 += g_ins_a[((l * 3 + ta) * BB + bsm[n]) * HH + hh];
        float* dst = (ta == 0) ? g_al : g_ar;
        dst[(node0 + n) * HH + hh] = a2;
    }
}

// ---------------- gather: warp per node; fused logit+exp+softmax+aggregate ----------------
__global__ __launch_bounds__(256) void gather_kernel(
    const float* __restrict__ x, const float* __restrict__ bias,
    const float* __restrict__ beta, float* __restrict__ dout,
    const int* __restrict__ ei, int l, int use_x, int bn_in, int do_bn_out) {
    int warp = threadIdx.x >> 5, lane = threadIdx.x & 31;
    int n = blockIdx.x * 8 + warp;
    const float* hin = use_x ? x : g_h;
    float* hout = do_bn_out ? g_h : dout;
    int s0 = g_start[n], s1 = g_start[n + 1];
    float2 arn = *(const float2*)&g_ar[n * 2];

    // chunk 0 (covers all edges when deg <= 32): per-lane logit -> exp
    int i = s0 + lane;
    int src = 0;
    float ex0 = 0.f, ex1 = 0.f;
    if (i < s1) {
        int e = g_csr[i];
        src = ei[e];
        float2 pe = *(const float2*)&g_pe[(l * EE + e) * 2];
        float2 al2 = *(const float2*)&g_al[src * 2];
        float a0 = pe.x + al2.x + arn.x;
        float a1 = pe.y + al2.y + arn.y;
        a0 = a0 > 0.f ? a0 : SLOPE * a0;
        a1 = a1 > 0.f ? a1 : SLOPE * a1;
        ex0 = __expf(a0);
        ex1 = __expf(a1);
    }
    float ss0 = ex0, ss1 = ex1;
    for (int base = s0 + 32; base < s1; base += 32) {   // rare (deg > 32)
        int j = base + lane;
        if (j < s1) {
            int e = g_csr[j];
            int sj = ei[e];
            float2 pe = *(const float2*)&g_pe[(l * EE + e) * 2];
            float2 al2 = *(const float2*)&g_al[sj * 2];
            float a0 = pe.x + al2.x + arn.x;
            float a1 = pe.y + al2.y + arn.y;
            a0 = a0 > 0.f ? a0 : SLOPE * a0;
            a1 = a1 > 0.f ? a1 : SLOPE * a1;
            ss0 += __expf(a0);
            ss1 += __expf(a1);
        }
    }
#pragma unroll
    for (int off = 16; off; off >>= 1) {
        ss0 += __shfl_xor_sync(0xffffffffu, ss0, off);
        ss1 += __shfl_xor_sync(0xffffffffu, ss1, off);
    }
    float inv0 = 0.5f / (ss0 + 1e-16f);
    float inv1 = 0.5f / (ss1 + 1e-16f);

    // accumulate: lane reads one float4 of the 128-float source row.
    // lanes 0-15 cover head0 (cols 0..63), lanes 16-31 head1 (cols 64..127).
    float4 acc = make_float4(0.f, 0.f, 0.f, 0.f);
    bool head0 = (lane < 16);
    int dc = s1 - s0; if (dc > 32) dc = 32;
    for (int k = 0; k < dc; k++) {
        float w0 = __shfl_sync(0xffffffffu, ex0, k) * inv0;
        float w1 = __shfl_sync(0xffffffffu, ex1, k) * inv1;
        int sj   = __shfl_sync(0xffffffffu, src, k);
        float w = head0 ? w0 : w1;
        float4 v = ((const float4*)(g_xl + sj * 128))[lane];
        acc.x += w * v.x; acc.y += w * v.y; acc.z += w * v.z; acc.w += w * v.w;
    }
    // rare tail: recompute ex per chunk (deterministic), then accumulate
    for (int base = s0 + 32; base < s1; base += 32) {
        int j = base + lane;
        int src2 = 0;
        float e0 = 0.f, e1 = 0.f;
        if (j < s1) {
            int e = g_csr[j];
            src2 = ei[e];
            float2 pe = *(const float2*)&g_pe[(l * EE + e) * 2];
            float2 al2 = *(const float2*)&g_al[src2 * 2];
            float a0 = pe.x + al2.x + arn.x;
            float a1 = pe.y + al2.y + arn.y;
            a0 = a0 > 0.f ? a0 : SLOPE * a0;
            a1 = a1 > 0.f ? a1 : SLOPE * a1;
            e0 = __expf(a0);
            e1 = __expf(a1);
        }
        int cnt = s1 - base; if (cnt > 32) cnt = 32;
        for (int k = 0; k < cnt; k++) {
            float w0 = __shfl_sync(0xffffffffu, e0, k) * inv0;
            float w1 = __shfl_sync(0xffffffffu, e1, k) * inv1;
            int sj   = __shfl_sync(0xffffffffu, src2, k);
            float w = head0 ? w0 : w1;
            float4 v = ((const float4*)(g_xl + sj * 128))[lane];
            acc.x += w * v.x; acc.y += w * v.y; acc.z += w * v.z; acc.w += w * v.w;
        }
    }

    // head mean: lane L (head0 part) + lane L+16 (head1 part) -> channels 4L..4L+3
    acc.x += __shfl_down_sync(0xffffffffu, acc.x, 16);
    acc.y += __shfl_down_sync(0xffffffffu, acc.y, 16);
    acc.z += __shfl_down_sync(0xffffffffu, acc.z, 16);
    acc.w += __shfl_down_sync(0xffffffffu, acc.w, 16);

    if (lane < 16) {
        float4 h4 = ((const float4*)(hin + n * DIN))[lane];
        if (bn_in) {
            float4 mu = ((const float4*)g_mu)[lane];
            float4 sc = ((const float4*)g_scale)[lane];
            float4 be = ((const float4*)beta)[lane];
            h4.x = (h4.x - mu.x) * sc.x + be.x; h4.x = h4.x > 0.f ? h4.x : 0.f;
            h4.y = (h4.y - mu.y) * sc.y + be.y; h4.y = h4.y > 0.f ? h4.y : 0.f;
            h4.z = (h4.z - mu.z) * sc.z + be.z; h4.z = h4.z > 0.f ? h4.z : 0.f;
            h4.w = (h4.w - mu.w) * sc.w + be.w; h4.w = h4.w > 0.f ? h4.w : 0.f;
        }
        float4 b4 = ((const float4*)(bias + l * CC))[lane];
        float4 o;
        o.x = acc.x + b4.x + h4.x;
        o.y = acc.y + b4.y + h4.y;
        o.z = acc.z + b4.z + h4.z;
        o.w = acc.w + b4.w + h4.w;
        ((float4*)(hout + n * DIN))[lane] = o;
    }
}

// ---------------- BN stats (deterministic two-stage) ----------------
__global__ __launch_bounds__(256) void bn_stats() {
    __shared__ float s1[256], s2m[256];
    int t = threadIdx.x;
    int c = t & 63, slot = t >> 6;
    float su = 0.f, sq = 0.f;
    for (int n = blockIdx.x * 4 + slot; n < NN; n += BN_BLOCKS * 4) {
        float v = g_h[n * DIN + c];
        su += v;
        sq += v * v;
    }
    s1[t] = su; s2m[t] = sq;
    __syncthreads();
    if (t < 64) {
        g_bnp[blockIdx.x * 64 + t]  = s1[t] + s1[t + 64] + s1[t + 128] + s1[t + 192];
        g_bnp2[blockIdx.x * 64 + t] = s2m[t] + s2m[t + 64] + s2m[t + 128] + s2m[t + 192];
    }
}

__global__ void bn_finalize(const float* __restrict__ gamma) {
    int c = threadIdx.x;
    if (c >= 64) return;
    float su = 0.f, sq = 0.f;
    for (int b = 0; b < BN_BLOCKS; b++) {
        su += g_bnp[b * 64 + c];
        sq += g_bnp2[b * 64 + c];
    }
    float mu = su / (float)NN;
    float var = sq / (float)NN - mu * mu;
    g_mu[c] = mu;
    g_scale[c] = gamma[c] * rsqrtf(var + EPSBN);
}

extern "C" void kernel_launch(void* const* d_in, const int* in_sizes, int n_in,
                              void* d_out, int out_size) {
    const float* x     = (const float*)d_in[0];
    const int*   ei    = (const int*)  d_in[1];
    const float* ea    = (const float*)d_in[2];
    const float* ins   = (const float*)d_in[3];
    const int*   batch = (const int*)  d_in[4];
    const float* Wl    = (const float*)d_in[5];
    const float* We    = (const float*)d_in[6];
    const float* attl  = (const float*)d_in[7];
    const float* attr_ = (const float*)d_in[8];
    const float* atte  = (const float*)d_in[9];
    const float* bias  = (const float*)d_in[10];
    const float* gamma = (const float*)d_in[11];
    const float* beta  = (const float*)d_in[12];
    float* out = (float*)d_out;

    prep_weights<<<SCAN_B, 256>>>(Wl, We, attl, attr_, atte);          // + zero cnt
    prep_ins<<<EE / 256, 256>>>(ins, Wl, ei);                          // + histogram
    scanA<<<SCAN_B, 256>>>();
    scanC<<<SCAN_B, 256>>>();
    place_kernel<<<EE / 256, 256>>>(ei);
    sort_kernel<<<NN / 8, 256>>>();
    edge_pre<<<EE / 8, 256>>>(ei, ea, batch);

    for (int l = 0; l < LL; l++) {
        int use_x = (l == 0);
        int bn_in = (l > 0);
        int do_bn_out = (l != LL - 1);
        node_kernel<<<NN / 16, 128>>>(x, batch, Wl, beta, l, use_x, bn_in);
        gather_kernel<<<NN / 8, 256>>>(x, bias, beta, out, ei, l, use_x, bn_in, do_bn_out);
        if (do_bn_out) {
            bn_stats<<<BN_BLOCKS, 256>>>();
            bn_finalize<<<1, 64>>>(gamma);
        }
    }
}